// round 15
// baseline (speedup 1.0000x reference)
#include <cuda_runtime.h>
#include <cuda_bf16.h>
#include <math.h>
#include <stdint.h>

// B=4, T=1024, C=2048, NH=16, HS=128, NLQ=512, NLKV=512, DHR=64

#if !defined(__CUDA_ARCH__) || defined(__CUDA_ARCH_SPECIFIC__) || \
    defined(__CUDA_ARCH_FEAT_SM103_ALL) || defined(__CUDA_ARCH_FEAT_SM100_ALL) || \
    defined(__CUDA_ARCH_FEAT_SM101_ALL)
#define HAS_TC 1
#else
#define HAS_TC 0
#endif

// ---------------- scratch --------------------------------------------------------
__device__ __nv_bfloat16 g_x2[2][4096L * 2048];
__device__ __nv_bfloat16 g_wca2[2][1280L * 2048];     // [W_dq;W_kr;W_dkv;pad]
__device__ __nv_bfloat16 g_wqr2[2][1024L * 512];
__device__ __nv_bfloat16 g_wuqT2[2][2048L * 512];
__device__ __nv_bfloat16 g_wuk2[2][2048L * 512];
__device__ __nv_bfloat16 g_wuvT2[2][512L * 2048];
__device__ __nv_bfloat16 g_wo2[2][2048L * 2048];
__device__ __nv_bfloat16 g_mt2[2][2048L * 512];
__device__ __nv_bfloat16 g_cqkv2[2][4096L * 1280];
__device__ float         g_mtp[2L * 2048 * 512];      // MT split-K partials
__device__ float         g_cqr[4096L * 1024];
__device__ __nv_bfloat16 g_qh2[2][64L * 1024 * 192];
__device__ __nv_bfloat16 g_kh2[2][64L * 1024 * 192];
__device__ __nv_bfloat16 g_vt2[2][64L * 128 * 1024];

// ---------------- PTX helpers ---------------------------------------------------
__device__ __forceinline__ uint32_t elect1() {
    uint32_t p;
    asm volatile("{\n\t.reg .pred p;\n\telect.sync _|p, 0xFFFFFFFF;\n\t"
                 "selp.b32 %0, 1, 0, p;\n\t}" : "=r"(p));
    return p;
}
__device__ __forceinline__ uint32_t s2u(const void* p) {
    uint32_t a;
    asm("{ .reg .u64 t; cvta.to.shared.u64 t, %1; cvt.u32.u64 %0, t; }" : "=r"(a) : "l"(p));
    return a;
}
#define TC_ALLOC(sm, n)  asm volatile("tcgen05.alloc.cta_group::1.sync.aligned.shared::cta.b32 [%0], %1;" :: "r"(sm), "r"(n) : "memory")
#define TC_DEALLOC(t, n) asm volatile("tcgen05.dealloc.cta_group::1.sync.aligned.b32 %0, %1;" :: "r"(t), "r"(n))
#define TC_RELINQ()      asm volatile("tcgen05.relinquish_alloc_permit.cta_group::1.sync.aligned;")
#define TC_COMMIT(mb)    asm volatile("tcgen05.commit.cta_group::1.mbarrier::arrive::one.shared::cluster.b64 [%0];" :: "r"(mb) : "memory")
#define TC_FENCE_AFTER() asm volatile("tcgen05.fence::after_thread_sync;" ::: "memory")
#define TC_FENCE_BEFORE() asm volatile("tcgen05.fence::before_thread_sync;" ::: "memory")
#define TC_WAIT_LD()     asm volatile("tcgen05.wait::ld.sync.aligned;" ::: "memory")
#define TC_WAIT_ST()     asm volatile("tcgen05.wait::st.sync.aligned;" ::: "memory")
#define FENCE_PROXY()    asm volatile("fence.proxy.async.shared::cta;" ::: "memory")
#define MB_INIT(mb, c)   asm volatile("mbarrier.init.shared.b64 [%0], %1;" :: "r"(mb), "r"(c) : "memory")
#define MB_WAIT(mb, ph) do { \
    asm volatile("{\n\t.reg .pred P1;\n\tWL_%=:\n\t" \
        "mbarrier.try_wait.parity.acquire.cta.shared::cta.b64 P1, [%0], %1, 0x989680;\n\t" \
        "@P1 bra.uni WD_%=;\n\tbra.uni WL_%=;\n\tWD_%=:\n\t}" \
        :: "r"(mb), "r"((uint32_t)(ph)) : "memory"); \
} while (0)
#define CP16(dst, src)   asm volatile("cp.async.cg.shared.global [%0], [%1], 16;" :: "r"(dst), "l"(src))
#define CP_COMMIT()      asm volatile("cp.async.commit_group;")
#define CP_WAIT(n)       asm volatile("cp.async.wait_group %0;" :: "n"(n))

#define TCLD32(r, a) \
    asm volatile("tcgen05.ld.sync.aligned.32x32b.x32.b32 " \
        "{%0,%1,%2,%3,%4,%5,%6,%7,%8,%9,%10,%11,%12,%13,%14,%15," \
        "%16,%17,%18,%19,%20,%21,%22,%23,%24,%25,%26,%27,%28,%29,%30,%31}, [%32];" \
        : "=r"((r)[0]),"=r"((r)[1]),"=r"((r)[2]),"=r"((r)[3]),"=r"((r)[4]),"=r"((r)[5]), \
          "=r"((r)[6]),"=r"((r)[7]),"=r"((r)[8]),"=r"((r)[9]),"=r"((r)[10]),"=r"((r)[11]), \
          "=r"((r)[12]),"=r"((r)[13]),"=r"((r)[14]),"=r"((r)[15]),"=r"((r)[16]),"=r"((r)[17]), \
          "=r"((r)[18]),"=r"((r)[19]),"=r"((r)[20]),"=r"((r)[21]),"=r"((r)[22]),"=r"((r)[23]), \
          "=r"((r)[24]),"=r"((r)[25]),"=r"((r)[26]),"=r"((r)[27]),"=r"((r)[28]),"=r"((r)[29]), \
          "=r"((r)[30]),"=r"((r)[31]) : "r"(a))

#define TCST32(a, r) \
    asm volatile("tcgen05.st.sync.aligned.32x32b.x32.b32 [%0], " \
        "{%1,%2,%3,%4,%5,%6,%7,%8,%9,%10,%11,%12,%13,%14,%15,%16," \
        "%17,%18,%19,%20,%21,%22,%23,%24,%25,%26,%27,%28,%29,%30,%31,%32};" \
        :: "r"(a), \
          "r"((r)[0]),"r"((r)[1]),"r"((r)[2]),"r"((r)[3]),"r"((r)[4]),"r"((r)[5]), \
          "r"((r)[6]),"r"((r)[7]),"r"((r)[8]),"r"((r)[9]),"r"((r)[10]),"r"((r)[11]), \
          "r"((r)[12]),"r"((r)[13]),"r"((r)[14]),"r"((r)[15]),"r"((r)[16]),"r"((r)[17]), \
          "r"((r)[18]),"r"((r)[19]),"r"((r)[20]),"r"((r)[21]),"r"((r)[22]),"r"((r)[23]), \
          "r"((r)[24]),"r"((r)[25]),"r"((r)[26]),"r"((r)[27]),"r"((r)[28]),"r"((r)[29]), \
          "r"((r)[30]),"r"((r)[31]) : "memory")

#if HAS_TC
__device__ __forceinline__ void mma_bf16_ss(uint32_t d, uint64_t a, uint64_t b,
                                            uint32_t idesc, bool en) {
    uint32_t e = en ? 1u : 0u;
    asm volatile("{\n\t.reg .pred p;\n\tsetp.ne.u32 p, %5, 0;\n\t"
        "tcgen05.mma.cta_group::1.kind::f16 [%0], %1, %2, %3, {%4, %4, %4, %4}, p;\n\t}"
        :: "r"(d), "l"(a), "l"(b), "r"(idesc), "r"(0u), "r"(e) : "memory");
}
__device__ __forceinline__ void mma_bf16_ts(uint32_t d, uint32_t a, uint64_t b,
                                            uint32_t idesc, bool en) {
    uint32_t e = en ? 1u : 0u;
    asm volatile("{\n\t.reg .pred p;\n\tsetp.ne.u32 p, %5, 0;\n\t"
        "tcgen05.mma.cta_group::1.kind::f16 [%0], [%1], %2, %3, {%4, %4, %4, %4}, p;\n\t}"
        :: "r"(d), "r"(a), "l"(b), "r"(idesc), "r"(0u), "r"(e) : "memory");
}
#endif

#define IDESC128 0x8200490u
#define IDESC256 0x8400490u
#define DESC_BASE ((2ULL << 61) | (1ULL << 46) | (64ULL << 32) | (1ULL << 16))
__device__ __forceinline__ uint64_t mkdesc(uint32_t addr) {
    return DESC_BASE | ((uint64_t)(addr >> 4) & 0x3FFF);
}
__device__ __forceinline__ uint32_t sw128(uint32_t b) { return b ^ ((b >> 3) & 0x70); }

__device__ __forceinline__ void bsplit(float v, __nv_bfloat16& h, __nv_bfloat16& l) {
    h = __float2bfloat16_rn(v);
    l = __float2bfloat16_rn(v - __bfloat162float(h));
}
__device__ __forceinline__ uint32_t bpack(__nv_bfloat16 a, __nv_bfloat16 b) {
    return (uint32_t)__bfloat16_as_ushort(a) | ((uint32_t)__bfloat16_as_ushort(b) << 16);
}

// ---------------- tcgen05 GEMM: persistent + cross-tile prefetch ----------------
#define ET_OFF 197632
#define ET_STRIDE 68
#define GSMEM 232448

template <int NT, bool WF32, bool WB16, bool HEADC>
__global__ void __launch_bounds__(256, 1) gemm_t6(
        const __nv_bfloat16* __restrict__ A, long long aPl,
        const __nv_bfloat16* __restrict__ B, long long bPl,
        float* __restrict__ Cf, __nv_bfloat16* __restrict__ Cb, long long cPl,
        int K, int lda, int ldb, int ldc,
        long long sAq, long long sAr, long long sBq, long long sBr,
        long long sCq, long long sCr, int zdiv, long long sHC,
        int tx, int ty, int tz) {
#if HAS_TC
    constexpr int S = (NT == 128) ? 3 : 2;
    constexpr int PB = NT * 128;
    constexpr int STG = 2 * 16384 + 2 * PB;
    constexpr int BPC = NT * 8;
    constexpr int ITER = (2048 + 2 * BPC) / 256;
    constexpr uint32_t ID = (NT == 128) ? IDESC128 : IDESC256;

    extern __shared__ __align__(1024) char smem[];
    const uint32_t smb = s2u(smem);
    const uint32_t mb0 = smb + 16, mb1 = smb + 24, mb2 = smb + 32;

    const int tid = threadIdx.x;
    const int warp = tid >> 5;
    const int lane = tid & 31;
    const int WT = tx * ty * tz;
    const int nt = K >> 6;

    if (warp == 0) TC_ALLOC(smb, NT);
    if (tid == 0) { MB_INIT(mb0, 1); MB_INIT(mb1, 1); MB_INIT(mb2, 1); }
    __syncthreads();
    uint32_t tmem;
    asm volatile("ld.shared.b32 %0, [%1];" : "=r"(tmem) : "r"(smb));

    int ph0 = 0, ph1 = 0, ph2 = 0;

    auto coords = [&](int w, int& m0, int& n0, const __nv_bfloat16*& Ab,
                      const __nv_bfloat16*& Bb, long long& cbase) {
        const int xt = w % tx;
        const int rw = w / tx;
        const int yt = rw % ty;
        const int z  = rw / ty;
        m0 = yt * 128; n0 = xt * NT;
        const int zq = z / zdiv, zr = z % zdiv;
        Ab = A + (long long)zq * sAq + (long long)zr * sAr;
        Bb = B + (long long)zq * sBq + (long long)zr * sBr;
        cbase = (long long)zq * sCq + (long long)zr * sCr +
                (HEADC ? (long long)xt * (NT / 128) * sHC : 0);
    };

    auto issue_load = [&](int c, const __nv_bfloat16* Ab, const __nv_bfloat16* Bb,
                          int m0, int n0) {
        const uint32_t st = smb + 1024 + (c % S) * STG;
        const int k0 = c << 6;
#pragma unroll
        for (int i = 0; i < ITER; i++) {
            int idx = tid + i * 256;
            if (idx < 2048) {
                int plane = idx >> 10, cc = idx & 1023;
                int r = cc >> 3, cq = cc & 7;
                CP16(st + plane * 16384 + sw128(r * 128 + cq * 16),
                     Ab + (long long)plane * aPl + (long long)(m0 + r) * lda + k0 + cq * 8);
            } else {
                int j = idx - 2048;
                int plane = j / BPC, cc = j % BPC;
                int r = cc >> 3, cq = cc & 7;
                CP16(st + 32768 + plane * PB + sw128(r * 128 + cq * 16),
                     Bb + (long long)plane * bPl + (long long)(n0 + r) * ldb + k0 + cq * 8);
            }
        }
        CP_COMMIT();
    };
    auto waitmma = [&](int j) {
        int bsel = j % 3;
        if (bsel == 0)      { MB_WAIT(mb0, ph0); ph0 ^= 1; }
        else if (bsel == 1) { MB_WAIT(mb1, ph1); ph1 ^= 1; }
        else                { MB_WAIT(mb2, ph2); ph2 ^= 1; }
    };

    int m0, n0; const __nv_bfloat16 *Ab, *Bb; long long cbase;
    int w = blockIdx.x;
    if (w < WT) {
        coords(w, m0, n0, Ab, Bb, cbase);
        for (int c = 0; c < S - 1 && c < nt; c++) issue_load(c, Ab, Bb, m0, n0);
    }

    for (; w < WT; w += gridDim.x) {
        coords(w, m0, n0, Ab, Bb, cbase);

        for (int c = 0; c < nt; c++) {
            if (c + 1 < nt) { CP_WAIT(S - 2); } else { CP_WAIT(0); }
            __syncthreads();
            FENCE_PROXY();
            if (warp == 0 && elect1()) {
                const uint32_t st = smb + 1024 + (c % S) * STG;
                uint64_t dAh = mkdesc(st);
                uint64_t dAl = mkdesc(st + 16384);
                uint64_t dBh = mkdesc(st + 32768);
                uint64_t dBl = mkdesc(st + 32768 + PB);
#pragma unroll
                for (int k = 0; k < 4; k++)
                    mma_bf16_ss(tmem, dAh + 2 * k, dBh + 2 * k, ID, !(c == 0 && k == 0));
#pragma unroll
                for (int k = 0; k < 4; k++)
                    mma_bf16_ss(tmem, dAh + 2 * k, dBl + 2 * k, ID, true);
#pragma unroll
                for (int k = 0; k < 4; k++)
                    mma_bf16_ss(tmem, dAl + 2 * k, dBh + 2 * k, ID, true);
                TC_COMMIT(smb + 16 + 8 * (c % 3));
            }
            if (c >= 1) waitmma(c - 1);
            if (c + S - 1 < nt) issue_load(c + S - 1, Ab, Bb, m0, n0);
        }
        waitmma(nt - 1);

        if (w + gridDim.x < WT) {
            int m0n, n0n; const __nv_bfloat16 *Abn, *Bbn; long long cbn;
            coords(w + gridDim.x, m0n, n0n, Abn, Bbn, cbn);
            for (int c = 0; c < S - 1 && c < nt; c++) issue_load(c, Abn, Bbn, m0n, n0n);
        }

        TC_FENCE_AFTER();
        float* et = (float*)(smem + ET_OFF);
#pragma unroll
        for (int p = 0; p < NT / 64; p++) {
            {
                const int rowg = warp & 3, colh = warp >> 2;
                uint32_t dr[32];
                TCLD32(dr, tmem + p * 64 + colh * 32);
                TC_WAIT_LD();
                float* q = et + (rowg * 32 + lane) * ET_STRIDE + colh * 32;
#pragma unroll
                for (int c = 0; c < 32; c++) q[c] = __uint_as_float(dr[c]);
            }
            __syncthreads();
#pragma unroll
            for (int i = 0; i < 8; i++) {
                int idx = tid + i * 256;
                int r = idx >> 4, qd = idx & 15;
                int gcol = p * 64 + qd * 4;
                const float* pp = et + r * ET_STRIDE + qd * 4;
                float4 v = make_float4(pp[0], pp[1], pp[2], pp[3]);
                long long hoff = (HEADC && gcol >= 128) ? sHC : 0;
                int col = HEADC ? (gcol & 127) : (n0 + gcol);
                long long off = cbase + hoff + (long long)(m0 + r) * ldc + col;
                if (WF32) *reinterpret_cast<float4*>(&Cf[off]) = v;
                if (WB16) {
                    __nv_bfloat16 hx, lx, hy, ly, hz, lz, hw, lw;
                    bsplit(v.x, hx, lx); bsplit(v.y, hy, ly);
                    bsplit(v.z, hz, lz); bsplit(v.w, hw, lw);
                    uint2 hi = make_uint2(bpack(hx, hy), bpack(hz, hw));
                    uint2 lo = make_uint2(bpack(lx, ly), bpack(lz, lw));
                    *reinterpret_cast<uint2*>(&Cb[off]) = hi;
                    *reinterpret_cast<uint2*>(&Cb[off + cPl]) = lo;
                }
            }
            __syncthreads();
        }
    }
    if (warp == 0) { TC_RELINQ(); TC_DEALLOC(tmem, NT); }
#endif
}

// ---------------- flash v3: S double-buffer, QK(t+1) overlaps softmax(t) --------
// TMEM: S0 0-127, O 128-255, P 256-383 (hi/lo), S1 384-511.
#define FQOFF 2048
#define FRING (FQOFF + 6 * 16384)     // 100352
#define FSMEM (FRING + 3 * 32768)     // 198656

__global__ void __launch_bounds__(256, 1) flash_attn(
        const __nv_bfloat16* __restrict__ qh, const __nv_bfloat16* __restrict__ kh,
        const __nv_bfloat16* __restrict__ vt, float* __restrict__ out) {
#if HAS_TC
    const long long QKPL = 64LL * 1024 * 192;
    const long long VPL  = 64LL * 128 * 1024;

    extern __shared__ __align__(1024) char smem[];
    const uint32_t smb = s2u(smem);
    const uint32_t mb0 = smb + 16, mb1 = smb + 24;
    float* ex = (float*)(smem + 32);

    const int tid = threadIdx.x, warp = tid >> 5, lane = tid & 31;
    const int ch = warp >> 2;
    const int row = (warp & 3) * 32 + lane;
    const int bx = blockIdx.x;

    if (warp == 0) TC_ALLOC(smb, 512);
    if (tid == 0) { MB_INIT(mb0, 1); MB_INIT(mb1, 1); }
    __syncthreads();
    uint32_t tmem;
    asm volatile("ld.shared.b32 %0, [%1];" : "=r"(tmem) : "r"(smb));
    const uint32_t tS0 = tmem, tO = tmem + 128, tP = tmem + 256, tS1 = tmem + 384;

    int ph0 = 0, ph1 = 0;
    auto waitmb = [&](int j) {
        if (j & 1) { MB_WAIT(mb1, ph1); ph1 ^= 1; }
        else       { MB_WAIT(mb0, ph0); ph0 ^= 1; }
    };

    for (int p = 0; p < 4; p++) {
        int item = p * 148 + ((p & 1) ? (147 - bx) : bx);
        if (item >= 512) continue;
        const int mt = 7 - (item >> 6);
        const int h = item & 15;
        const int b = (item >> 4) & 3;
        const int ntile = mt + 1, m0 = mt * 128;
        const int S = 5 * ntile;
        const __nv_bfloat16* Qb = qh + (long long)(b * 16 + h) * (1024LL * 192);
        const __nv_bfloat16* Kb = kh + (long long)(b * 16 + h) * (1024LL * 192);
        const __nv_bfloat16* Vb = vt + (long long)(b * 16 + h) * (128LL * 1024);

        // Q resident (3 chunks x hi/lo)
        {
#pragma unroll
            for (int i = 0; i < 24; i++) {
                int idx = tid + i * 256;
                int cp = idx >> 10;
                int c = cp >> 1, pl = cp & 1;
                int cidx = idx & 1023, rr = cidx >> 3, cc = cidx & 7;
                const __nv_bfloat16* src = Qb + (long long)pl * QKPL +
                    (long long)(m0 + rr) * 192 + c * 64 + cc * 8;
                CP16(smb + FQOFF + cp * 16384 + sw128(rr * 128 + cc * 16), src);
            }
            CP_COMMIT();
        }

        // slot s -> (isK, tile, chunk); order: K0, then per group g: K(g+1), V(g)
        auto slot_info = [&](int s, int& isK, int& t, int& c) {
            if (s < 3) { isK = 1; t = 0; c = s; return; }
            int sp = s - 3, g = sp / 5, r = sp % 5;
            if (g + 1 < ntile) {
                if (r < 3) { isK = 1; t = g + 1; c = r; }
                else       { isK = 0; t = g;     c = r - 3; }
            } else       { isK = 0; t = g;     c = r; }
        };
        auto issue_slot = [&](int s) {
            int isK, t, r;
            slot_info(s, isK, t, r);
            uint32_t dst = smb + FRING + (s % 3) * 32768;
#pragma unroll
            for (int i = 0; i < 8; i++) {
                int idx = tid + i * 256;
                int pl = idx >> 10, cidx = idx & 1023, rr = cidx >> 3, cc = cidx & 7;
                const __nv_bfloat16* src;
                if (isK)
                    src = Kb + (long long)pl * QKPL + (long long)(t * 128 + rr) * 192 + r * 64 + cc * 8;
                else
                    src = Vb + (long long)pl * VPL + (long long)rr * 1024 + t * 128 + r * 64 + cc * 8;
                CP16(dst + pl * 16384 + sw128(rr * 128 + cc * 16), src);
            }
            CP_COMMIT();
        };
        issue_slot(0);
        if (S > 1) issue_slot(1);

        float m_old = -INFINITY, lsum = 0.0f;
        int sc = 0, waited = -1;

        // one ring chunk: consume slot sc; QK (into tSd) or PV
        auto chunk_qk = [&](int c, uint32_t tSd, bool first) {
            if (sc + 1 < S) { CP_WAIT(1); } else { CP_WAIT(0); }
            __syncthreads();
            FENCE_PROXY();
            if (warp == 0 && elect1()) {
                uint32_t st = smb + FRING + (sc % 3) * 32768;
                uint64_t dQh = mkdesc(smb + FQOFF + (c * 2 + 0) * 16384);
                uint64_t dQl = mkdesc(smb + FQOFF + (c * 2 + 1) * 16384);
                uint64_t dKh = mkdesc(st);
                uint64_t dKl = mkdesc(st + 16384);
#pragma unroll
                for (int k = 0; k < 4; k++)
                    mma_bf16_ss(tSd, dQh + 2 * k, dKh + 2 * k, IDESC128, !(first && k == 0));
#pragma unroll
                for (int k = 0; k < 4; k++)
                    mma_bf16_ss(tSd, dQh + 2 * k, dKl + 2 * k, IDESC128, true);
#pragma unroll
                for (int k = 0; k < 4; k++)
                    mma_bf16_ss(tSd, dQl + 2 * k, dKh + 2 * k, IDESC128, true);
                TC_COMMIT((sc & 1) ? mb1 : mb0);
            }
            while (waited < sc - 1) { waited++; waitmb(waited); }
            if (sc + 2 < S) issue_slot(sc + 2);
            sc++;
        };
        auto chunk_pv = [&](int vc, bool first) {
            if (sc + 1 < S) { CP_WAIT(1); } else { CP_WAIT(0); }
            __syncthreads();
            FENCE_PROXY();
            if (warp == 0 && elect1()) {
                TC_FENCE_AFTER();
                uint32_t st = smb + FRING + (sc % 3) * 32768;
                uint32_t aH = tP + vc * 32;
                uint32_t aL = tP + 64 + vc * 32;
                uint64_t dVh = mkdesc(st);
                uint64_t dVl = mkdesc(st + 16384);
#pragma unroll
                for (int k = 0; k < 4; k++)
                    mma_bf16_ts(tO, aH + 8 * k, dVh + 2 * k, IDESC128, !(first && k == 0));
#pragma unroll
                for (int k = 0; k < 4; k++)
                    mma_bf16_ts(tO, aH + 8 * k, dVl + 2 * k, IDESC128, true);
#pragma unroll
                for (int k = 0; k < 4; k++)
                    mma_bf16_ts(tO, aL + 8 * k, dVh + 2 * k, IDESC128, true);
                TC_COMMIT((sc & 1) ? mb1 : mb0);
            }
            while (waited < sc - 1) { waited++; waitmb(waited); }
            if (sc + 2 < S) issue_slot(sc + 2);
            sc++;
        };

        // QK(0) into S0
        for (int c = 0; c < 3; c++) chunk_qk(c, tS0, c == 0);

        for (int t = 0; t < ntile; t++) {
            // wait all MMAs issued so far (QK(t) + PV(t-1))
            while (waited < sc - 1) { waited++; waitmb(waited); }
            TC_FENCE_AFTER();

            const uint32_t tSr = (t & 1) ? tS1 : tS0;
            float sv[64];
            {
                uint32_t r0[32], r1[32];
                TCLD32(r0, tSr + ch * 64);
                TCLD32(r1, tSr + ch * 64 + 32);
                TC_WAIT_LD();
                const float scale = 0.07216878364870323f;
#pragma unroll
                for (int j = 0; j < 32; j++) {
                    sv[j] = __uint_as_float(r0[j]) * scale;
                    sv[32 + j] = __uint_as_float(r1[j]) * scale;
                }
            }
            // kick QK(t+1) into the other S buffer while we do softmax(t)
            if (t + 1 < ntile) {
                const uint32_t tSn = ((t + 1) & 1) ? tS1 : tS0;
                for (int c = 0; c < 3; c++) chunk_qk(c, tSn, c == 0);
            }

            if (t == mt) {
#pragma unroll
                for (int j = 0; j < 64; j++)
                    if (ch * 64 + j > row) sv[j] = -INFINITY;
            }
            float pmax = -INFINITY;
#pragma unroll
            for (int j = 0; j < 64; j++) pmax = fmaxf(pmax, sv[j]);
            __syncthreads();
            ex[warp * 32 + lane] = pmax;
            __syncthreads();
            float m_new = fmaxf(m_old, fmaxf(pmax, ex[(warp ^ 4) * 32 + lane]));
            float alpha = __expf(m_old - m_new);
            bool norescale = (t == 0) || __all_sync(0xffffffffu, m_new == m_old);
            float psum = 0.0f;
#pragma unroll
            for (int j = 0; j < 64; j++) { sv[j] = __expf(sv[j] - m_new); psum += sv[j]; }
            __syncthreads();
            ex[warp * 32 + lane] = psum;
            __syncthreads();
            lsum = lsum * alpha + psum + ex[(warp ^ 4) * 32 + lane];
            m_old = m_new;

            // P -> TMEM
            {
                uint32_t hw[32], lw[32];
#pragma unroll
                for (int j = 0; j < 32; j++) {
                    __nv_bfloat16 ah, al, bh, bl;
                    bsplit(sv[2 * j], ah, al);
                    bsplit(sv[2 * j + 1], bh, bl);
                    hw[j] = bpack(ah, bh);
                    lw[j] = bpack(al, bl);
                }
                TCST32(tP + ch * 32, hw);
                TCST32(tP + 64 + ch * 32, lw);
            }
            if (!norescale) {          // safe: PV(t-1) completed at loop top
                uint32_t r0[32], r1[32];
                TCLD32(r0, tO + ch * 64);
                TCLD32(r1, tO + ch * 64 + 32);
                TC_WAIT_LD();
#pragma unroll
                for (int j = 0; j < 32; j++) {
                    r0[j] = __float_as_uint(__uint_as_float(r0[j]) * alpha);
                    r1[j] = __float_as_uint(__uint_as_float(r1[j]) * alpha);
                }
                TCST32(tO + ch * 64, r0);
                TCST32(tO + ch * 64 + 32, r1);
            }
            TC_WAIT_ST();
            FENCE_PROXY();
            TC_FENCE_BEFORE();
            __syncthreads();

            // PV(t)
            for (int vc = 0; vc < 2; vc++) chunk_pv(vc, t == 0 && vc == 0);
        }
        while (waited < sc - 1) { waited++; waitmb(waited); }
        TC_FENCE_AFTER();
        {
            uint32_t r0[32], r1[32];
            TCLD32(r0, tO + ch * 64);
            TCLD32(r1, tO + ch * 64 + 32);
            TC_WAIT_LD();
            float inv = 1.0f / lsum;
            float* op = out + ((long long)(b * 1024 + m0 + row)) * 2048 + h * 128 + ch * 64;
#pragma unroll
            for (int j = 0; j < 8; j++) {
                float4 v = make_float4(__uint_as_float(r0[4*j]) * inv, __uint_as_float(r0[4*j+1]) * inv,
                                       __uint_as_float(r0[4*j+2]) * inv, __uint_as_float(r0[4*j+3]) * inv);
                *reinterpret_cast<float4*>(op + 4 * j) = v;
                float4 w = make_float4(__uint_as_float(r1[4*j]) * inv, __uint_as_float(r1[4*j+1]) * inv,
                                       __uint_as_float(r1[4*j+2]) * inv, __uint_as_float(r1[4*j+3]) * inv);
                *reinterpret_cast<float4*>(op + 32 + 4 * j) = w;
            }
        }
        __syncthreads();
    }
    if (warp == 0) { TC_RELINQ(); TC_DEALLOC(tmem, 512); }
#endif
}

// ---------------- vectorized prep ------------------------------------------------
__global__ void prep_all4(const float* __restrict__ x, const float* __restrict__ wqr,
                          const float* __restrict__ wuk, const float* __restrict__ wo,
                          const float* __restrict__ Wdq, const float* __restrict__ Wkr,
                          const float* __restrict__ Wdkv,
                          __nv_bfloat16* __restrict__ ox, __nv_bfloat16* __restrict__ oqr,
                          __nv_bfloat16* __restrict__ ouk, __nv_bfloat16* __restrict__ owo,
                          __nv_bfloat16* __restrict__ owca,
                          long long px, long long pqr, long long puk, long long pwo,
                          long long pwca) {
    long long i4 = (long long)blockIdx.x * blockDim.x + threadIdx.x;
    if (i4 >= 4194304) return;
    float4 v; __nv_bfloat16* dst; long long pl, j;
    if (i4 < 2097152)      { j = i4 * 4; v = reinterpret_cast<const float4*>(x)[i4]; dst = ox; pl = px; }
    else if (i4 < 2228224) { long long k = i4 - 2097152; j = k * 4;
                             v = reinterpret_cast<const float4*>(wqr)[k]; dst = oqr; pl = pqr; }
    else if (i4 < 2490368) { long long k = i4 - 2228224; j = k * 4;
                             v = reinterpret_cast<const float4*>(wuk)[k]; dst = ouk; pl = puk; }
    else if (i4 < 3538944) { long long k = i4 - 2490368; j = k * 4;
                             v = reinterpret_cast<const float4*>(wo)[k]; dst = owo; pl = pwo; }
    else {
        long long k = i4 - 3538944; j = k * 4;
        int rw = (int)(j >> 11), col = (int)(j & 2047);
        if (rw < 512)       v = *reinterpret_cast<const float4*>(&Wdq[rw * 2048 + col]);
        else if (rw < 576)  v = *reinterpret_cast<const float4*>(&Wkr[(rw - 512) * 2048 + col]);
        else if (rw < 1088) v = *reinterpret_cast<const float4*>(&Wdkv[(rw - 576) * 2048 + col]);
        else                v = make_float4(0.f, 0.f, 0.f, 0.f);
        dst = owca; pl = pwca;
    }
    __nv_bfloat16 h0, l0, h1, l1, h2, l2, h3, l3;
    bsplit(v.x, h0, l0); bsplit(v.y, h1, l1); bsplit(v.z, h2, l2); bsplit(v.w, h3, l3);
    *reinterpret_cast<uint2*>(&dst[j]) = make_uint2(bpack(h0, h1), bpack(h2, h3));
    *reinterpret_cast<uint2*>(&dst[j + pl]) = make_uint2(bpack(l0, l1), bpack(l2, l3));
}

__global__ void transpose_all(const float* __restrict__ wuq, const float* __restrict__ wuv,
                              __nv_bfloat16* __restrict__ oq, __nv_bfloat16* __restrict__ ov,
                              long long pq, long long pv) {
    __shared__ float tile[32][33];
    const float* in; __nv_bfloat16* out; long long oPl; int R, C, bx, by;
    int bid = blockIdx.x;
    if (bid < 1024) { in = wuq; out = oq; oPl = pq; R = 512;  C = 2048;
                      bx = (bid & 63) * 32; by = (bid >> 6) * 32; }
    else            { bid -= 1024; in = wuv; out = ov; oPl = pv; R = 2048; C = 512;
                      bx = (bid & 15) * 32; by = (bid >> 4) * 32; }
    int tx = threadIdx.x, ty = threadIdx.y;
#pragma unroll
    for (int i = 0; i < 4; i++)
        tile[ty + i * 8][tx] = in[(long long)(by + ty + i * 8) * C + bx + tx];
    __syncthreads();
#pragma unroll
    for (int i = 0; i < 4; i++) {
        int c = bx + ty + i * 8, r = by + tx;
        __nv_bfloat16 h, l; bsplit(tile[tx][ty + i * 8], h, l);
        out[(long long)c * R + r] = h;
        out[(long long)c * R + r + oPl] = l;
    }
}

__global__ void reduce_mt(const float* __restrict__ p, __nv_bfloat16* __restrict__ out,
                          long long oPl) {
    int i = blockIdx.x * blockDim.x + threadIdx.x;
    if (i >= 262144) return;
    float4 a = reinterpret_cast<const float4*>(p)[i];
    float4 b = reinterpret_cast<const float4*>(p + 1048576)[i];
    a.x += b.x; a.y += b.y; a.z += b.z; a.w += b.w;
    __nv_bfloat16 h0, l0, h1, l1, h2, l2, h3, l3;
    bsplit(a.x, h0, l0); bsplit(a.y, h1, l1); bsplit(a.z, h2, l2); bsplit(a.w, h3, l3);
    long long j = (long long)i * 4;
    *reinterpret_cast<uint2*>(&out[j]) = make_uint2(bpack(h0, h1), bpack(h2, h3));
    *reinterpret_cast<uint2*>(&out[j + oPl]) = make_uint2(bpack(l0, l1), bpack(l2, l3));
}

// ---------------- rope ----------------------------------------------------------
__global__ void rope_q_kernel(const float* __restrict__ cqr, const float* __restrict__ fc,
                              const float* __restrict__ fs, __nv_bfloat16* __restrict__ qh,
                              long long qPl) {
    int idx = blockIdx.x * blockDim.x + threadIdx.x;
    if (idx >= 4 * 1024 * 16 * 32) return;
    int j = idx & 31;
    int h = (idx >> 5) & 15;
    int t = (idx >> 9) & 1023;
    int b = idx >> 19;
    long long src = (((long long)(b * 1024 + t)) * 1024) + h * 64 + 2 * j;
    float re = cqr[src], im = cqr[src + 1];
    float c = fc[t * 32 + j], s = fs[t * 32 + j];
    float o0 = re * c - im * s, o1 = re * s + im * c;
    long long dst = (((long long)(b * 16 + h)) * 1024 + t) * 192 + 128 + 2 * j;
    __nv_bfloat16 h0, l0, h1, l1; bsplit(o0, h0, l0); bsplit(o1, h1, l1);
    qh[dst] = h0; qh[dst + qPl] = l0;
    qh[dst + 1] = h1; qh[dst + 1 + qPl] = l1;
}

__global__ void rope_k_kernel(const __nv_bfloat16* __restrict__ cqkv2, long long cPl,
                              const float* __restrict__ fc, const float* __restrict__ fs,
                              __nv_bfloat16* __restrict__ kh, long long kPl) {
    int idx = blockIdx.x * blockDim.x + threadIdx.x;
    if (idx >= 4 * 1024 * 32) return;
    int j = idx & 31;
    int t = (idx >> 5) & 1023;
    int b = idx >> 15;
    long long src = ((long long)(b * 1024 + t)) * 1280 + 512 + 2 * j;
    float re = __bfloat162float(cqkv2[src]) + __bfloat162float(cqkv2[src + cPl]);
    float im = __bfloat162float(cqkv2[src + 1]) + __bfloat162float(cqkv2[src + 1 + cPl]);
    float c = fc[t * 32 + j], s = fs[t * 32 + j];
    float o0 = re * c - im * s, o1 = re * s + im * c;
    __nv_bfloat16 h0, l0, h1, l1; bsplit(o0, h0, l0); bsplit(o1, h1, l1);
#pragma unroll
    for (int h = 0; h < 16; h++) {
        long long dst = (((long long)(b * 16 + h)) * 1024 + t) * 192 + 128 + 2 * j;
        kh[dst] = h0; kh[dst + kPl] = l0;
        kh[dst + 1] = h1; kh[dst + 1 + kPl] = l1;
    }
}

// ---------------- launcher -------------------------------------------------------
extern "C" void kernel_launch(void* const* d_in, const int* in_sizes, int n_in,
                              void* d_out, int out_size) {
    (void)in_sizes; (void)n_in; (void)out_size;
    const float* x     = (const float*)d_in[0];
    const float* W_dq  = (const float*)d_in[1];
    const float* W_uq  = (const float*)d_in[2];
    const float* W_dkv = (const float*)d_in[3];
    const float* W_uk  = (const float*)d_in[4];
    const float* W_uv  = (const float*)d_in[5];
    const float* W_o   = (const float*)d_in[6];
    const float* W_qr  = (const float*)d_in[7];
    const float* W_kr  = (const float*)d_in[8];
    const float* fc    = (const float*)d_in[9];
    const float* fs    = (const float*)d_in[10];
    float* out = (float*)d_out;

    __nv_bfloat16 *x2, *wca2, *wqr2, *wuqT2, *wuk2, *wuvT2, *wo2, *mt2;
    __nv_bfloat16 *cqkv2, *qh2, *kh2, *vt2;
    float *mtp, *cqr;
    cudaGetSymbolAddress((void**)&x2,     g_x2);
    cudaGetSymbolAddress((void**)&wca2,   g_wca2);
    cudaGetSymbolAddress((void**)&wqr2,   g_wqr2);
    cudaGetSymbolAddress((void**)&wuqT2,  g_wuqT2);
    cudaGetSymbolAddress((void**)&wuk2,   g_wuk2);
    cudaGetSymbolAddress((void**)&wuvT2,  g_wuvT2);
    cudaGetSymbolAddress((void**)&wo2,    g_wo2);
    cudaGetSymbolAddress((void**)&mt2,    g_mt2);
    cudaGetSymbolAddress((void**)&cqkv2,  g_cqkv2);
    cudaGetSymbolAddress((void**)&mtp,    g_mtp);
    cudaGetSymbolAddress((void**)&cqr,    g_cqr);
    cudaGetSymbolAddress((void**)&qh2,    g_qh2);
    cudaGetSymbolAddress((void**)&kh2,    g_kh2);
    cudaGetSymbolAddress((void**)&vt2,    g_vt2);

    const long long XPL    = 4096LL * 2048;
    const long long WCAPL  = 1280LL * 2048;
    const long long WQRPL  = 1024LL * 512;
    const long long WUQPL  = 2048LL * 512;
    const long long WUKPL  = 2048LL * 512;
    const long long WUVPL  = 512LL * 2048;
    const long long WOPL   = 2048LL * 2048;
    const long long MTPL   = 2048LL * 512;
    const long long CQKVPL = 4096LL * 1280;
    const long long HPL    = 64LL * 1024 * 192;
    const long long VTPL   = 64LL * 128 * 1024;
    const long long HZ     = 1024LL * 192;
    const long long VTZ    = 128LL * 1024;

    cudaFuncSetAttribute(gemm_t6<256, false, true,  false>, cudaFuncAttributeMaxDynamicSharedMemorySize, GSMEM);
    cudaFuncSetAttribute(gemm_t6<256, true,  false, false>, cudaFuncAttributeMaxDynamicSharedMemorySize, GSMEM);
    cudaFuncSetAttribute(gemm_t6<256, false, true,  true >, cudaFuncAttributeMaxDynamicSharedMemorySize, GSMEM);
    cudaFuncSetAttribute(flash_attn, cudaFuncAttributeMaxDynamicSharedMemorySize, FSMEM);

    dim3 blk(256);

    // --- prep (2 launches) ---
    prep_all4<<<16384, 256>>>(x, W_qr, W_uk, W_o, W_dq, W_kr, W_dkv,
                              x2, wqr2, wuk2, wo2, wca2,
                              XPL, WQRPL, WUKPL, WOPL, WCAPL);
    transpose_all<<<2048, dim3(32, 8)>>>(W_uq, W_uv, wuqT2, wuvT2, WUQPL, WUVPL);

    // 1) cqkv (4096x1280) = x @ Wall^T   [planes]
    gemm_t6<256, false, true, false><<<148, blk, GSMEM>>>(
        x2, XPL, wca2, WCAPL, nullptr, cqkv2, CQKVPL,
        2048, 2048, 2048, 1280, 0, 0, 0, 0, 0, 0, 1, 0, 5, 32, 1);

    // 2) MT: NT=256, split-K x2 -> partials, then reduce -> planes
    gemm_t6<256, true, false, false><<<64, blk, GSMEM>>>(
        wo2, WOPL, wuvT2, WUVPL, mtp, nullptr, 0,
        1024, 2048, 2048, 512,
        1024, 0, 1024, 0, 1048576LL, 0, 1, 0, 2, 16, 2);
    reduce_mt<<<1024, 256>>>(mtp, mt2, MTPL);

    // 3) c_qr (4096x1024) = c_q @ W_qr^T [f32]
    gemm_t6<256, true, false, false><<<128, blk, GSMEM>>>(
        cqkv2, CQKVPL, wqr2, WQRPL, cqr, nullptr, 0,
        512, 1280, 512, 1024, 0, 0, 0, 0, 0, 0, 1, 0, 4, 32, 1);

    // 4+5) qh AND kh in ONE persistent launch (z<4: qh from Wuq; z>=4: kh from Wuk)
    gemm_t6<256, false, true, true><<<148, blk, GSMEM>>>(
        cqkv2, CQKVPL, wuqT2, WUQPL, nullptr, qh2, HPL,
        512, 1280, 512, 192,
        576, 1024LL * 1280,
        (long long)(wuk2 - wuqT2), 0,
        (long long)(kh2 - qh2), 16LL * HZ, 4, HZ, 8, 8, 8);

    // 6) rope tails
    rope_q_kernel<<<8192, 256>>>(cqr, fc, fs, qh2, HPL);
    rope_k_kernel<<<512, 256>>>(cqkv2, CQKVPL, fc, fs, kh2, HPL);

    // 7) VT[b,h] (128x1024) = MT[h-slice] @ c_kv[b]^T
    gemm_t6<256, false, true, false><<<148, blk, GSMEM>>>(
        mt2, MTPL, cqkv2 + 576, CQKVPL, nullptr, vt2, VTPL,
        512, 512, 1280, 1024,
        0, 128LL * 512, 1024LL * 1280, 0, 16LL * VTZ, VTZ, 16, 0, 4, 1, 64);

    // 8) fused flash attention
    flash_attn<<<148, blk, FSMEM>>>(qh2, kh2, vt2, out);
}

// round 16
// speedup vs baseline: 1.0415x; 1.0415x over previous
#include <cuda_runtime.h>
#include <cuda_bf16.h>
#include <math.h>
#include <stdint.h>

// B=4, T=1024, C=2048, NH=16, HS=128, NLQ=512, NLKV=512, DHR=64

#if !defined(__CUDA_ARCH__) || defined(__CUDA_ARCH_SPECIFIC__) || \
    defined(__CUDA_ARCH_FEAT_SM103_ALL) || defined(__CUDA_ARCH_FEAT_SM100_ALL) || \
    defined(__CUDA_ARCH_FEAT_SM101_ALL)
#define HAS_TC 1
#else
#define HAS_TC 0
#endif

// ---------------- scratch --------------------------------------------------------
__device__ __nv_bfloat16 g_x2[2][4096L * 2048];
__device__ __nv_bfloat16 g_wca2[2][1280L * 2048];     // [W_dq;W_kr;W_dkv;pad]
__device__ __nv_bfloat16 g_wqr2[2][1024L * 512];
__device__ __nv_bfloat16 g_wuqT2[2][2048L * 512];
__device__ __nv_bfloat16 g_wuk2[2][2048L * 512];
__device__ __nv_bfloat16 g_wuvT2[2][512L * 2048];
__device__ __nv_bfloat16 g_wo2[2][2048L * 2048];
__device__ __nv_bfloat16 g_mt2[2][2048L * 512];
__device__ __nv_bfloat16 g_cqkv2[2][4096L * 1280];
__device__ float         g_mtp[2L * 2048 * 512];      // MT split-K partials
__device__ __nv_bfloat16 g_cqr2[2][4096L * 1024];     // c_qr hi/lo planes
__device__ __nv_bfloat16 g_qh2[2][64L * 1024 * 192];
__device__ __nv_bfloat16 g_kh2[2][64L * 1024 * 192];
__device__ __nv_bfloat16 g_vt2[2][64L * 128 * 1024];

// ---------------- PTX helpers ---------------------------------------------------
__device__ __forceinline__ uint32_t elect1() {
    uint32_t p;
    asm volatile("{\n\t.reg .pred p;\n\telect.sync _|p, 0xFFFFFFFF;\n\t"
                 "selp.b32 %0, 1, 0, p;\n\t}" : "=r"(p));
    return p;
}
__device__ __forceinline__ uint32_t s2u(const void* p) {
    uint32_t a;
    asm("{ .reg .u64 t; cvta.to.shared.u64 t, %1; cvt.u32.u64 %0, t; }" : "=r"(a) : "l"(p));
    return a;
}
#define TC_ALLOC(sm, n)  asm volatile("tcgen05.alloc.cta_group::1.sync.aligned.shared::cta.b32 [%0], %1;" :: "r"(sm), "r"(n) : "memory")
#define TC_DEALLOC(t, n) asm volatile("tcgen05.dealloc.cta_group::1.sync.aligned.b32 %0, %1;" :: "r"(t), "r"(n))
#define TC_RELINQ()      asm volatile("tcgen05.relinquish_alloc_permit.cta_group::1.sync.aligned;")
#define TC_COMMIT(mb)    asm volatile("tcgen05.commit.cta_group::1.mbarrier::arrive::one.shared::cluster.b64 [%0];" :: "r"(mb) : "memory")
#define TC_FENCE_AFTER() asm volatile("tcgen05.fence::after_thread_sync;" ::: "memory")
#define TC_FENCE_BEFORE() asm volatile("tcgen05.fence::before_thread_sync;" ::: "memory")
#define TC_WAIT_LD()     asm volatile("tcgen05.wait::ld.sync.aligned;" ::: "memory")
#define TC_WAIT_ST()     asm volatile("tcgen05.wait::st.sync.aligned;" ::: "memory")
#define FENCE_PROXY()    asm volatile("fence.proxy.async.shared::cta;" ::: "memory")
#define MB_INIT(mb, c)   asm volatile("mbarrier.init.shared.b64 [%0], %1;" :: "r"(mb), "r"(c) : "memory")
#define MB_WAIT(mb, ph) do { \
    asm volatile("{\n\t.reg .pred P1;\n\tWL_%=:\n\t" \
        "mbarrier.try_wait.parity.acquire.cta.shared::cta.b64 P1, [%0], %1, 0x989680;\n\t" \
        "@P1 bra.uni WD_%=;\n\tbra.uni WL_%=;\n\tWD_%=:\n\t}" \
        :: "r"(mb), "r"((uint32_t)(ph)) : "memory"); \
} while (0)
#define CP16(dst, src)   asm volatile("cp.async.cg.shared.global [%0], [%1], 16;" :: "r"(dst), "l"(src))
#define CP_COMMIT()      asm volatile("cp.async.commit_group;")
#define CP_WAIT(n)       asm volatile("cp.async.wait_group %0;" :: "n"(n))

#define TCLD32(r, a) \
    asm volatile("tcgen05.ld.sync.aligned.32x32b.x32.b32 " \
        "{%0,%1,%2,%3,%4,%5,%6,%7,%8,%9,%10,%11,%12,%13,%14,%15," \
        "%16,%17,%18,%19,%20,%21,%22,%23,%24,%25,%26,%27,%28,%29,%30,%31}, [%32];" \
        : "=r"((r)[0]),"=r"((r)[1]),"=r"((r)[2]),"=r"((r)[3]),"=r"((r)[4]),"=r"((r)[5]), \
          "=r"((r)[6]),"=r"((r)[7]),"=r"((r)[8]),"=r"((r)[9]),"=r"((r)[10]),"=r"((r)[11]), \
          "=r"((r)[12]),"=r"((r)[13]),"=r"((r)[14]),"=r"((r)[15]),"=r"((r)[16]),"=r"((r)[17]), \
          "=r"((r)[18]),"=r"((r)[19]),"=r"((r)[20]),"=r"((r)[21]),"=r"((r)[22]),"=r"((r)[23]), \
          "=r"((r)[24]),"=r"((r)[25]),"=r"((r)[26]),"=r"((r)[27]),"=r"((r)[28]),"=r"((r)[29]), \
          "=r"((r)[30]),"=r"((r)[31]) : "r"(a))

#define TCST32(a, r) \
    asm volatile("tcgen05.st.sync.aligned.32x32b.x32.b32 [%0], " \
        "{%1,%2,%3,%4,%5,%6,%7,%8,%9,%10,%11,%12,%13,%14,%15,%16," \
        "%17,%18,%19,%20,%21,%22,%23,%24,%25,%26,%27,%28,%29,%30,%31,%32};" \
        :: "r"(a), \
          "r"((r)[0]),"r"((r)[1]),"r"((r)[2]),"r"((r)[3]),"r"((r)[4]),"r"((r)[5]), \
          "r"((r)[6]),"r"((r)[7]),"r"((r)[8]),"r"((r)[9]),"r"((r)[10]),"r"((r)[11]), \
          "r"((r)[12]),"r"((r)[13]),"r"((r)[14]),"r"((r)[15]),"r"((r)[16]),"r"((r)[17]), \
          "r"((r)[18]),"r"((r)[19]),"r"((r)[20]),"r"((r)[21]),"r"((r)[22]),"r"((r)[23]), \
          "r"((r)[24]),"r"((r)[25]),"r"((r)[26]),"r"((r)[27]),"r"((r)[28]),"r"((r)[29]), \
          "r"((r)[30]),"r"((r)[31]) : "memory")

#if HAS_TC
__device__ __forceinline__ void mma_bf16_ss(uint32_t d, uint64_t a, uint64_t b,
                                            uint32_t idesc, bool en) {
    uint32_t e = en ? 1u : 0u;
    asm volatile("{\n\t.reg .pred p;\n\tsetp.ne.u32 p, %5, 0;\n\t"
        "tcgen05.mma.cta_group::1.kind::f16 [%0], %1, %2, %3, {%4, %4, %4, %4}, p;\n\t}"
        :: "r"(d), "l"(a), "l"(b), "r"(idesc), "r"(0u), "r"(e) : "memory");
}
__device__ __forceinline__ void mma_bf16_ts(uint32_t d, uint32_t a, uint64_t b,
                                            uint32_t idesc, bool en) {
    uint32_t e = en ? 1u : 0u;
    asm volatile("{\n\t.reg .pred p;\n\tsetp.ne.u32 p, %5, 0;\n\t"
        "tcgen05.mma.cta_group::1.kind::f16 [%0], [%1], %2, %3, {%4, %4, %4, %4}, p;\n\t}"
        :: "r"(d), "r"(a), "l"(b), "r"(idesc), "r"(0u), "r"(e) : "memory");
}
#endif

#define IDESC128 0x8200490u
#define IDESC256 0x8400490u
#define DESC_BASE ((2ULL << 61) | (1ULL << 46) | (64ULL << 32) | (1ULL << 16))
__device__ __forceinline__ uint64_t mkdesc(uint32_t addr) {
    return DESC_BASE | ((uint64_t)(addr >> 4) & 0x3FFF);
}
__device__ __forceinline__ uint32_t sw128(uint32_t b) { return b ^ ((b >> 3) & 0x70); }

__device__ __forceinline__ void bsplit(float v, __nv_bfloat16& h, __nv_bfloat16& l) {
    h = __float2bfloat16_rn(v);
    l = __float2bfloat16_rn(v - __bfloat162float(h));
}
__device__ __forceinline__ uint32_t bpack(__nv_bfloat16 a, __nv_bfloat16 b) {
    return (uint32_t)__bfloat16_as_ushort(a) | ((uint32_t)__bfloat16_as_ushort(b) << 16);
}

// ---------------- tcgen05 GEMM: persistent + cross-tile prefetch ----------------
#define ET_OFF 197632
#define ET_STRIDE 68
#define GSMEM 232448

template <int NT, bool WF32, bool WB16, bool HEADC>
__global__ void __launch_bounds__(256, 1) gemm_t6(
        const __nv_bfloat16* __restrict__ A, long long aPl,
        const __nv_bfloat16* __restrict__ B, long long bPl,
        float* __restrict__ Cf, __nv_bfloat16* __restrict__ Cb, long long cPl,
        int K, int lda, int ldb, int ldc,
        long long sAq, long long sAr, long long sBq, long long sBr,
        long long sCq, long long sCr, int zdiv, long long sHC,
        int tx, int ty, int tz) {
#if HAS_TC
    constexpr int S = (NT == 128) ? 3 : 2;
    constexpr int PB = NT * 128;
    constexpr int STG = 2 * 16384 + 2 * PB;
    constexpr int BPC = NT * 8;
    constexpr int ITER = (2048 + 2 * BPC) / 256;
    constexpr uint32_t ID = (NT == 128) ? IDESC128 : IDESC256;

    extern __shared__ __align__(1024) char smem[];
    const uint32_t smb = s2u(smem);
    const uint32_t mb0 = smb + 16, mb1 = smb + 24, mb2 = smb + 32;

    const int tid = threadIdx.x;
    const int warp = tid >> 5;
    const int lane = tid & 31;
    const int WT = tx * ty * tz;
    const int nt = K >> 6;

    if (warp == 0) TC_ALLOC(smb, NT);
    if (tid == 0) { MB_INIT(mb0, 1); MB_INIT(mb1, 1); MB_INIT(mb2, 1); }
    __syncthreads();
    uint32_t tmem;
    asm volatile("ld.shared.b32 %0, [%1];" : "=r"(tmem) : "r"(smb));

    int ph0 = 0, ph1 = 0, ph2 = 0;

    auto coords = [&](int w, int& m0, int& n0, const __nv_bfloat16*& Ab,
                      const __nv_bfloat16*& Bb, long long& cbase) {
        const int xt = w % tx;
        const int rw = w / tx;
        const int yt = rw % ty;
        const int z  = rw / ty;
        m0 = yt * 128; n0 = xt * NT;
        const int zq = z / zdiv, zr = z % zdiv;
        Ab = A + (long long)zq * sAq + (long long)zr * sAr;
        Bb = B + (long long)zq * sBq + (long long)zr * sBr;
        cbase = (long long)zq * sCq + (long long)zr * sCr +
                (HEADC ? (long long)xt * (NT / 128) * sHC : 0);
    };

    auto issue_load = [&](int c, const __nv_bfloat16* Ab, const __nv_bfloat16* Bb,
                          int m0, int n0) {
        const uint32_t st = smb + 1024 + (c % S) * STG;
        const int k0 = c << 6;
#pragma unroll
        for (int i = 0; i < ITER; i++) {
            int idx = tid + i * 256;
            if (idx < 2048) {
                int plane = idx >> 10, cc = idx & 1023;
                int r = cc >> 3, cq = cc & 7;
                CP16(st + plane * 16384 + sw128(r * 128 + cq * 16),
                     Ab + (long long)plane * aPl + (long long)(m0 + r) * lda + k0 + cq * 8);
            } else {
                int j = idx - 2048;
                int plane = j / BPC, cc = j % BPC;
                int r = cc >> 3, cq = cc & 7;
                CP16(st + 32768 + plane * PB + sw128(r * 128 + cq * 16),
                     Bb + (long long)plane * bPl + (long long)(n0 + r) * ldb + k0 + cq * 8);
            }
        }
        CP_COMMIT();
    };
    auto waitmma = [&](int j) {
        int bsel = j % 3;
        if (bsel == 0)      { MB_WAIT(mb0, ph0); ph0 ^= 1; }
        else if (bsel == 1) { MB_WAIT(mb1, ph1); ph1 ^= 1; }
        else                { MB_WAIT(mb2, ph2); ph2 ^= 1; }
    };

    int m0, n0; const __nv_bfloat16 *Ab, *Bb; long long cbase;
    int w = blockIdx.x;
    if (w < WT) {
        coords(w, m0, n0, Ab, Bb, cbase);
        for (int c = 0; c < S - 1 && c < nt; c++) issue_load(c, Ab, Bb, m0, n0);
    }

    for (; w < WT; w += gridDim.x) {
        coords(w, m0, n0, Ab, Bb, cbase);

        for (int c = 0; c < nt; c++) {
            if (c + 1 < nt) { CP_WAIT(S - 2); } else { CP_WAIT(0); }
            __syncthreads();
            FENCE_PROXY();
            if (warp == 0 && elect1()) {
                const uint32_t st = smb + 1024 + (c % S) * STG;
                uint64_t dAh = mkdesc(st);
                uint64_t dAl = mkdesc(st + 16384);
                uint64_t dBh = mkdesc(st + 32768);
                uint64_t dBl = mkdesc(st + 32768 + PB);
#pragma unroll
                for (int k = 0; k < 4; k++)
                    mma_bf16_ss(tmem, dAh + 2 * k, dBh + 2 * k, ID, !(c == 0 && k == 0));
#pragma unroll
                for (int k = 0; k < 4; k++)
                    mma_bf16_ss(tmem, dAh + 2 * k, dBl + 2 * k, ID, true);
#pragma unroll
                for (int k = 0; k < 4; k++)
                    mma_bf16_ss(tmem, dAl + 2 * k, dBh + 2 * k, ID, true);
                TC_COMMIT(smb + 16 + 8 * (c % 3));
            }
            if (c >= 1) waitmma(c - 1);
            if (c + S - 1 < nt) issue_load(c + S - 1, Ab, Bb, m0, n0);
        }
        waitmma(nt - 1);

        if (w + gridDim.x < WT) {
            int m0n, n0n; const __nv_bfloat16 *Abn, *Bbn; long long cbn;
            coords(w + gridDim.x, m0n, n0n, Abn, Bbn, cbn);
            for (int c = 0; c < S - 1 && c < nt; c++) issue_load(c, Abn, Bbn, m0n, n0n);
        }

        TC_FENCE_AFTER();
        float* et = (float*)(smem + ET_OFF);
#pragma unroll
        for (int p = 0; p < NT / 64; p++) {
            {
                const int rowg = warp & 3, colh = warp >> 2;
                uint32_t dr[32];
                TCLD32(dr, tmem + p * 64 + colh * 32);
                TC_WAIT_LD();
                float* q = et + (rowg * 32 + lane) * ET_STRIDE + colh * 32;
#pragma unroll
                for (int c = 0; c < 32; c++) q[c] = __uint_as_float(dr[c]);
            }
            __syncthreads();
#pragma unroll
            for (int i = 0; i < 8; i++) {
                int idx = tid + i * 256;
                int r = idx >> 4, qd = idx & 15;
                int gcol = p * 64 + qd * 4;
                const float* pp = et + r * ET_STRIDE + qd * 4;
                float4 v = make_float4(pp[0], pp[1], pp[2], pp[3]);
                long long hoff = (HEADC && gcol >= 128) ? sHC : 0;
                int col = HEADC ? (gcol & 127) : (n0 + gcol);
                long long off = cbase + hoff + (long long)(m0 + r) * ldc + col;
                if (WF32) *reinterpret_cast<float4*>(&Cf[off]) = v;
                if (WB16) {
                    __nv_bfloat16 hx, lx, hy, ly, hz, lz, hw, lw;
                    bsplit(v.x, hx, lx); bsplit(v.y, hy, ly);
                    bsplit(v.z, hz, lz); bsplit(v.w, hw, lw);
                    uint2 hi = make_uint2(bpack(hx, hy), bpack(hz, hw));
                    uint2 lo = make_uint2(bpack(lx, ly), bpack(lz, lw));
                    *reinterpret_cast<uint2*>(&Cb[off]) = hi;
                    *reinterpret_cast<uint2*>(&Cb[off + cPl]) = lo;
                }
            }
            __syncthreads();
        }
    }
    if (warp == 0) { TC_RELINQ(); TC_DEALLOC(tmem, NT); }
#endif
}

// ---------------- flash (R14 proven): 3-slot ring, lag-1 waits, P in TMEM -------
// TMEM: S cols 0-127, O cols 128-255, P hi 256-319, P lo 320-383 (alloc 512).
#define FQOFF 2048
#define FRING (FQOFF + 6 * 16384)     // 100352
#define FSMEM (FRING + 3 * 32768)     // 198656

__global__ void __launch_bounds__(256, 1) flash_attn(
        const __nv_bfloat16* __restrict__ qh, const __nv_bfloat16* __restrict__ kh,
        const __nv_bfloat16* __restrict__ vt, float* __restrict__ out) {
#if HAS_TC
    const long long QKPL = 64LL * 1024 * 192;
    const long long VPL  = 64LL * 128 * 1024;

    extern __shared__ __align__(1024) char smem[];
    const uint32_t smb = s2u(smem);
    const uint32_t mb0 = smb + 16, mb1 = smb + 24;
    float* ex = (float*)(smem + 32);

    const int tid = threadIdx.x, warp = tid >> 5, lane = tid & 31;
    const int ch = warp >> 2;
    const int row = (warp & 3) * 32 + lane;
    const int bx = blockIdx.x;

    if (warp == 0) TC_ALLOC(smb, 512);
    if (tid == 0) { MB_INIT(mb0, 1); MB_INIT(mb1, 1); }
    __syncthreads();
    uint32_t tmem;
    asm volatile("ld.shared.b32 %0, [%1];" : "=r"(tmem) : "r"(smb));
    const uint32_t tS = tmem, tO = tmem + 128, tP = tmem + 256;

    int ph0 = 0, ph1 = 0;
    auto waitmb = [&](int j) {
        if (j & 1) { MB_WAIT(mb1, ph1); ph1 ^= 1; }
        else       { MB_WAIT(mb0, ph0); ph0 ^= 1; }
    };

    for (int p = 0; p < 4; p++) {
        int item = p * 148 + ((p & 1) ? (147 - bx) : bx);
        if (item >= 512) continue;
        const int mt = 7 - (item >> 6);
        const int h = item & 15;
        const int b = (item >> 4) & 3;
        const int ntile = mt + 1, m0 = mt * 128;
        const int S = 5 * ntile;
        const __nv_bfloat16* Qb = qh + (long long)(b * 16 + h) * (1024LL * 192);
        const __nv_bfloat16* Kb = kh + (long long)(b * 16 + h) * (1024LL * 192);
        const __nv_bfloat16* Vb = vt + (long long)(b * 16 + h) * (128LL * 1024);

        {
#pragma unroll
            for (int i = 0; i < 24; i++) {
                int idx = tid + i * 256;
                int cp = idx >> 10;
                int c = cp >> 1, pl = cp & 1;
                int cidx = idx & 1023, rr = cidx >> 3, cc = cidx & 7;
                const __nv_bfloat16* src = Qb + (long long)pl * QKPL +
                    (long long)(m0 + rr) * 192 + c * 64 + cc * 8;
                CP16(smb + FQOFF + cp * 16384 + sw128(rr * 128 + cc * 16), src);
            }
            CP_COMMIT();
        }
        auto issue_slot = [&](int s) {
            int t = s / 5, r = s % 5;
            uint32_t dst = smb + FRING + (s % 3) * 32768;
#pragma unroll
            for (int i = 0; i < 8; i++) {
                int idx = tid + i * 256;
                int pl = idx >> 10, cidx = idx & 1023, rr = cidx >> 3, cc = cidx & 7;
                const __nv_bfloat16* src;
                if (r < 3)
                    src = Kb + (long long)pl * QKPL + (long long)(t * 128 + rr) * 192 + r * 64 + cc * 8;
                else
                    src = Vb + (long long)pl * VPL + (long long)rr * 1024 + t * 128 + (r - 3) * 64 + cc * 8;
                CP16(dst + pl * 16384 + sw128(rr * 128 + cc * 16), src);
            }
            CP_COMMIT();
        };
        issue_slot(0);
        if (S > 1) issue_slot(1);

        float m_old = -INFINITY, lsum = 0.0f;
        int sc = 0, waited = -1;

        for (int t = 0; t < ntile; t++) {
            for (int c = 0; c < 3; c++) {
                if (sc + 1 < S) { CP_WAIT(1); } else { CP_WAIT(0); }
                __syncthreads();
                FENCE_PROXY();
                if (warp == 0 && elect1()) {
                    uint32_t st = smb + FRING + (sc % 3) * 32768;
                    uint64_t dQh = mkdesc(smb + FQOFF + (c * 2 + 0) * 16384);
                    uint64_t dQl = mkdesc(smb + FQOFF + (c * 2 + 1) * 16384);
                    uint64_t dKh = mkdesc(st);
                    uint64_t dKl = mkdesc(st + 16384);
#pragma unroll
                    for (int k = 0; k < 4; k++)
                        mma_bf16_ss(tS, dQh + 2 * k, dKh + 2 * k, IDESC128, !(c == 0 && k == 0));
#pragma unroll
                    for (int k = 0; k < 4; k++)
                        mma_bf16_ss(tS, dQh + 2 * k, dKl + 2 * k, IDESC128, true);
#pragma unroll
                    for (int k = 0; k < 4; k++)
                        mma_bf16_ss(tS, dQl + 2 * k, dKh + 2 * k, IDESC128, true);
                    TC_COMMIT((sc & 1) ? mb1 : mb0);
                }
                while (waited < sc - 1) { waited++; waitmb(waited); }
                if (sc + 2 < S) issue_slot(sc + 2);
                sc++;
            }
            while (waited < sc - 1) { waited++; waitmb(waited); }
            TC_FENCE_AFTER();

            float sv[64];
            {
                uint32_t r0[32], r1[32];
                TCLD32(r0, tS + ch * 64);
                TCLD32(r1, tS + ch * 64 + 32);
                TC_WAIT_LD();
                const float scale = 0.07216878364870323f;
#pragma unroll
                for (int j = 0; j < 32; j++) {
                    sv[j] = __uint_as_float(r0[j]) * scale;
                    sv[32 + j] = __uint_as_float(r1[j]) * scale;
                }
            }
            if (t == mt) {
#pragma unroll
                for (int j = 0; j < 64; j++)
                    if (ch * 64 + j > row) sv[j] = -INFINITY;
            }
            float pmax = -INFINITY;
#pragma unroll
            for (int j = 0; j < 64; j++) pmax = fmaxf(pmax, sv[j]);
            __syncthreads();
            ex[warp * 32 + lane] = pmax;
            __syncthreads();
            float m_new = fmaxf(m_old, fmaxf(pmax, ex[(warp ^ 4) * 32 + lane]));
            float alpha = __expf(m_old - m_new);
            bool norescale = (t == 0) || __all_sync(0xffffffffu, m_new == m_old);
            float psum = 0.0f;
#pragma unroll
            for (int j = 0; j < 64; j++) { sv[j] = __expf(sv[j] - m_new); psum += sv[j]; }
            __syncthreads();
            ex[warp * 32 + lane] = psum;
            __syncthreads();
            lsum = lsum * alpha + psum + ex[(warp ^ 4) * 32 + lane];
            m_old = m_new;

            {
                uint32_t hw[32], lw[32];
#pragma unroll
                for (int j = 0; j < 32; j++) {
                    __nv_bfloat16 ah, al, bh, bl;
                    bsplit(sv[2 * j], ah, al);
                    bsplit(sv[2 * j + 1], bh, bl);
                    hw[j] = bpack(ah, bh);
                    lw[j] = bpack(al, bl);
                }
                TCST32(tP + ch * 32, hw);
                TCST32(tP + 64 + ch * 32, lw);
            }
            if (!norescale) {
                uint32_t r0[32], r1[32];
                TCLD32(r0, tO + ch * 64);
                TCLD32(r1, tO + ch * 64 + 32);
                TC_WAIT_LD();
#pragma unroll
                for (int j = 0; j < 32; j++) {
                    r0[j] = __float_as_uint(__uint_as_float(r0[j]) * alpha);
                    r1[j] = __float_as_uint(__uint_as_float(r1[j]) * alpha);
                }
                TCST32(tO + ch * 64, r0);
                TCST32(tO + ch * 64 + 32, r1);
            }
            TC_WAIT_ST();
            FENCE_PROXY();
            TC_FENCE_BEFORE();
            __syncthreads();

            for (int vc = 0; vc < 2; vc++) {
                if (sc + 1 < S) { CP_WAIT(1); } else { CP_WAIT(0); }
                __syncthreads();
                FENCE_PROXY();
                if (warp == 0 && elect1()) {
                    TC_FENCE_AFTER();
                    uint32_t st = smb + FRING + (sc % 3) * 32768;
                    uint32_t aH = tP + vc * 32;
                    uint32_t aL = tP + 64 + vc * 32;
                    uint64_t dVh = mkdesc(st);
                    uint64_t dVl = mkdesc(st + 16384);
#pragma unroll
                    for (int k = 0; k < 4; k++)
                        mma_bf16_ts(tO, aH + 8 * k, dVh + 2 * k, IDESC128, !(t == 0 && vc == 0 && k == 0));
#pragma unroll
                    for (int k = 0; k < 4; k++)
                        mma_bf16_ts(tO, aH + 8 * k, dVl + 2 * k, IDESC128, true);
#pragma unroll
                    for (int k = 0; k < 4; k++)
                        mma_bf16_ts(tO, aL + 8 * k, dVh + 2 * k, IDESC128, true);
                    TC_COMMIT((sc & 1) ? mb1 : mb0);
                }
                while (waited < sc - 1) { waited++; waitmb(waited); }
                if (sc + 2 < S) issue_slot(sc + 2);
                sc++;
            }
        }
        while (waited < sc - 1) { waited++; waitmb(waited); }
        TC_FENCE_AFTER();
        {
            uint32_t r0[32], r1[32];
            TCLD32(r0, tO + ch * 64);
            TCLD32(r1, tO + ch * 64 + 32);
            TC_WAIT_LD();
            float inv = 1.0f / lsum;
            float* op = out + ((long long)(b * 1024 + m0 + row)) * 2048 + h * 128 + ch * 64;
#pragma unroll
            for (int j = 0; j < 8; j++) {
                float4 v = make_float4(__uint_as_float(r0[4*j]) * inv, __uint_as_float(r0[4*j+1]) * inv,
                                       __uint_as_float(r0[4*j+2]) * inv, __uint_as_float(r0[4*j+3]) * inv);
                *reinterpret_cast<float4*>(op + 4 * j) = v;
                float4 w = make_float4(__uint_as_float(r1[4*j]) * inv, __uint_as_float(r1[4*j+1]) * inv,
                                       __uint_as_float(r1[4*j+2]) * inv, __uint_as_float(r1[4*j+3]) * inv);
                *reinterpret_cast<float4*>(op + 32 + 4 * j) = w;
            }
        }
        __syncthreads();
    }
    if (warp == 0) { TC_RELINQ(); TC_DEALLOC(tmem, 512); }
#endif
}

// ---------------- vectorized prep ------------------------------------------------
__global__ void prep_all4(const float* __restrict__ x, const float* __restrict__ wqr,
                          const float* __restrict__ wuk, const float* __restrict__ wo,
                          const float* __restrict__ Wdq, const float* __restrict__ Wkr,
                          const float* __restrict__ Wdkv,
                          __nv_bfloat16* __restrict__ ox, __nv_bfloat16* __restrict__ oqr,
                          __nv_bfloat16* __restrict__ ouk, __nv_bfloat16* __restrict__ owo,
                          __nv_bfloat16* __restrict__ owca,
                          long long px, long long pqr, long long puk, long long pwo,
                          long long pwca) {
    long long i4 = (long long)blockIdx.x * blockDim.x + threadIdx.x;
    if (i4 >= 4194304) return;
    float4 v; __nv_bfloat16* dst; long long pl, j;
    if (i4 < 2097152)      { j = i4 * 4; v = reinterpret_cast<const float4*>(x)[i4]; dst = ox; pl = px; }
    else if (i4 < 2228224) { long long k = i4 - 2097152; j = k * 4;
                             v = reinterpret_cast<const float4*>(wqr)[k]; dst = oqr; pl = pqr; }
    else if (i4 < 2490368) { long long k = i4 - 2228224; j = k * 4;
                             v = reinterpret_cast<const float4*>(wuk)[k]; dst = ouk; pl = puk; }
    else if (i4 < 3538944) { long long k = i4 - 2490368; j = k * 4;
                             v = reinterpret_cast<const float4*>(wo)[k]; dst = owo; pl = pwo; }
    else {
        long long k = i4 - 3538944; j = k * 4;
        int rw = (int)(j >> 11), col = (int)(j & 2047);
        if (rw < 512)       v = *reinterpret_cast<const float4*>(&Wdq[rw * 2048 + col]);
        else if (rw < 576)  v = *reinterpret_cast<const float4*>(&Wkr[(rw - 512) * 2048 + col]);
        else if (rw < 1088) v = *reinterpret_cast<const float4*>(&Wdkv[(rw - 576) * 2048 + col]);
        else                v = make_float4(0.f, 0.f, 0.f, 0.f);
        dst = owca; pl = pwca;
    }
    __nv_bfloat16 h0, l0, h1, l1, h2, l2, h3, l3;
    bsplit(v.x, h0, l0); bsplit(v.y, h1, l1); bsplit(v.z, h2, l2); bsplit(v.w, h3, l3);
    *reinterpret_cast<uint2*>(&dst[j]) = make_uint2(bpack(h0, h1), bpack(h2, h3));
    *reinterpret_cast<uint2*>(&dst[j + pl]) = make_uint2(bpack(l0, l1), bpack(l2, l3));
}

__global__ void transpose_all(const float* __restrict__ wuq, const float* __restrict__ wuv,
                              __nv_bfloat16* __restrict__ oq, __nv_bfloat16* __restrict__ ov,
                              long long pq, long long pv) {
    __shared__ float tile[32][33];
    const float* in; __nv_bfloat16* out; long long oPl; int R, C, bx, by;
    int bid = blockIdx.x;
    if (bid < 1024) { in = wuq; out = oq; oPl = pq; R = 512;  C = 2048;
                      bx = (bid & 63) * 32; by = (bid >> 6) * 32; }
    else            { bid -= 1024; in = wuv; out = ov; oPl = pv; R = 2048; C = 512;
                      bx = (bid & 15) * 32; by = (bid >> 4) * 32; }
    int tx = threadIdx.x, ty = threadIdx.y;
#pragma unroll
    for (int i = 0; i < 4; i++)
        tile[ty + i * 8][tx] = in[(long long)(by + ty + i * 8) * C + bx + tx];
    __syncthreads();
#pragma unroll
    for (int i = 0; i < 4; i++) {
        int c = bx + ty + i * 8, r = by + tx;
        __nv_bfloat16 h, l; bsplit(tile[tx][ty + i * 8], h, l);
        out[(long long)c * R + r] = h;
        out[(long long)c * R + r + oPl] = l;
    }
}

__global__ void reduce_mt(const float* __restrict__ p, __nv_bfloat16* __restrict__ out,
                          long long oPl) {
    int i = blockIdx.x * blockDim.x + threadIdx.x;
    if (i >= 262144) return;
    float4 a = reinterpret_cast<const float4*>(p)[i];
    float4 b = reinterpret_cast<const float4*>(p + 1048576)[i];
    a.x += b.x; a.y += b.y; a.z += b.z; a.w += b.w;
    __nv_bfloat16 h0, l0, h1, l1, h2, l2, h3, l3;
    bsplit(a.x, h0, l0); bsplit(a.y, h1, l1); bsplit(a.z, h2, l2); bsplit(a.w, h3, l3);
    long long j = (long long)i * 4;
    *reinterpret_cast<uint2*>(&out[j]) = make_uint2(bpack(h0, h1), bpack(h2, h3));
    *reinterpret_cast<uint2*>(&out[j + oPl]) = make_uint2(bpack(l0, l1), bpack(l2, l3));
}

// ---------------- rope ----------------------------------------------------------
__global__ void rope_q_kernel(const __nv_bfloat16* __restrict__ cqr2, long long cPl,
                              const float* __restrict__ fc, const float* __restrict__ fs,
                              __nv_bfloat16* __restrict__ qh, long long qPl) {
    int idx = blockIdx.x * blockDim.x + threadIdx.x;
    if (idx >= 4 * 1024 * 16 * 32) return;
    int j = idx & 31;
    int h = (idx >> 5) & 15;
    int t = (idx >> 9) & 1023;
    int b = idx >> 19;
    long long src = (((long long)(b * 1024 + t)) * 1024) + h * 64 + 2 * j;
    float re = __bfloat162float(cqr2[src]) + __bfloat162float(cqr2[src + cPl]);
    float im = __bfloat162float(cqr2[src + 1]) + __bfloat162float(cqr2[src + 1 + cPl]);
    float c = fc[t * 32 + j], s = fs[t * 32 + j];
    float o0 = re * c - im * s, o1 = re * s + im * c;
    long long dst = (((long long)(b * 16 + h)) * 1024 + t) * 192 + 128 + 2 * j;
    __nv_bfloat16 h0, l0, h1, l1; bsplit(o0, h0, l0); bsplit(o1, h1, l1);
    qh[dst] = h0; qh[dst + qPl] = l0;
    qh[dst + 1] = h1; qh[dst + 1 + qPl] = l1;
}

__global__ void rope_k_kernel(const __nv_bfloat16* __restrict__ cqkv2, long long cPl,
                              const float* __restrict__ fc, const float* __restrict__ fs,
                              __nv_bfloat16* __restrict__ kh, long long kPl) {
    int idx = blockIdx.x * blockDim.x + threadIdx.x;
    if (idx >= 4 * 1024 * 32) return;
    int j = idx & 31;
    int t = (idx >> 5) & 1023;
    int b = idx >> 15;
    long long src = ((long long)(b * 1024 + t)) * 1280 + 512 + 2 * j;
    float re = __bfloat162float(cqkv2[src]) + __bfloat162float(cqkv2[src + cPl]);
    float im = __bfloat162float(cqkv2[src + 1]) + __bfloat162float(cqkv2[src + 1 + cPl]);
    float c = fc[t * 32 + j], s = fs[t * 32 + j];
    float o0 = re * c - im * s, o1 = re * s + im * c;
    __nv_bfloat16 h0, l0, h1, l1; bsplit(o0, h0, l0); bsplit(o1, h1, l1);
#pragma unroll
    for (int h = 0; h < 16; h++) {
        long long dst = (((long long)(b * 16 + h)) * 1024 + t) * 192 + 128 + 2 * j;
        kh[dst] = h0; kh[dst + kPl] = l0;
        kh[dst + 1] = h1; kh[dst + 1 + kPl] = l1;
    }
}

// ---------------- launcher -------------------------------------------------------
extern "C" void kernel_launch(void* const* d_in, const int* in_sizes, int n_in,
                              void* d_out, int out_size) {
    (void)in_sizes; (void)n_in; (void)out_size;
    const float* x     = (const float*)d_in[0];
    const float* W_dq  = (const float*)d_in[1];
    const float* W_uq  = (const float*)d_in[2];
    const float* W_dkv = (const float*)d_in[3];
    const float* W_uk  = (const float*)d_in[4];
    const float* W_uv  = (const float*)d_in[5];
    const float* W_o   = (const float*)d_in[6];
    const float* W_qr  = (const float*)d_in[7];
    const float* W_kr  = (const float*)d_in[8];
    const float* fc    = (const float*)d_in[9];
    const float* fs    = (const float*)d_in[10];
    float* out = (float*)d_out;

    __nv_bfloat16 *x2, *wca2, *wqr2, *wuqT2, *wuk2, *wuvT2, *wo2, *mt2;
    __nv_bfloat16 *cqkv2, *cqr2, *qh2, *kh2, *vt2;
    float *mtp;
    cudaGetSymbolAddress((void**)&x2,     g_x2);
    cudaGetSymbolAddress((void**)&wca2,   g_wca2);
    cudaGetSymbolAddress((void**)&wqr2,   g_wqr2);
    cudaGetSymbolAddress((void**)&wuqT2,  g_wuqT2);
    cudaGetSymbolAddress((void**)&wuk2,   g_wuk2);
    cudaGetSymbolAddress((void**)&wuvT2,  g_wuvT2);
    cudaGetSymbolAddress((void**)&wo2,    g_wo2);
    cudaGetSymbolAddress((void**)&mt2,    g_mt2);
    cudaGetSymbolAddress((void**)&cqkv2,  g_cqkv2);
    cudaGetSymbolAddress((void**)&mtp,    g_mtp);
    cudaGetSymbolAddress((void**)&cqr2,   g_cqr2);
    cudaGetSymbolAddress((void**)&qh2,    g_qh2);
    cudaGetSymbolAddress((void**)&kh2,    g_kh2);
    cudaGetSymbolAddress((void**)&vt2,    g_vt2);

    const long long XPL    = 4096LL * 2048;
    const long long WCAPL  = 1280LL * 2048;
    const long long WQRPL  = 1024LL * 512;
    const long long WUQPL  = 2048LL * 512;
    const long long WUKPL  = 2048LL * 512;
    const long long WUVPL  = 512LL * 2048;
    const long long WOPL   = 2048LL * 2048;
    const long long MTPL   = 2048LL * 512;
    const long long CQKVPL = 4096LL * 1280;
    const long long CQRPL  = 4096LL * 1024;
    const long long HPL    = 64LL * 1024 * 192;
    const long long VTPL   = 64LL * 128 * 1024;
    const long long HZ     = 1024LL * 192;
    const long long VTZ    = 128LL * 1024;

    cudaFuncSetAttribute(gemm_t6<256, false, true,  false>, cudaFuncAttributeMaxDynamicSharedMemorySize, GSMEM);
    cudaFuncSetAttribute(gemm_t6<128, true,  false, false>, cudaFuncAttributeMaxDynamicSharedMemorySize, GSMEM);
    cudaFuncSetAttribute(gemm_t6<256, false, true,  true >, cudaFuncAttributeMaxDynamicSharedMemorySize, GSMEM);
    cudaFuncSetAttribute(flash_attn, cudaFuncAttributeMaxDynamicSharedMemorySize, FSMEM);

    dim3 blk(256);

    // --- prep (2 launches) ---
    prep_all4<<<16384, 256>>>(x, W_qr, W_uk, W_o, W_dq, W_kr, W_dkv,
                              x2, wqr2, wuk2, wo2, wca2,
                              XPL, WQRPL, WUKPL, WOPL, WCAPL);
    transpose_all<<<2048, dim3(32, 8)>>>(W_uq, W_uv, wuqT2, wuvT2, WUQPL, WUVPL);

    // 1) cqkv (4096x1280) = x @ Wall^T   [planes]
    gemm_t6<256, false, true, false><<<148, blk, GSMEM>>>(
        x2, XPL, wca2, WCAPL, nullptr, cqkv2, CQKVPL,
        2048, 2048, 2048, 1280, 0, 0, 0, 0, 0, 0, 1, 0, 5, 32, 1);

    // 2) MT: NT=128 split-K x2 (R14 config) -> partials, then reduce
    gemm_t6<128, true, false, false><<<128, blk, GSMEM>>>(
        wo2, WOPL, wuvT2, WUVPL, mtp, nullptr, 0,
        1024, 2048, 2048, 512,
        0, 1024, 0, 1024, 0, 1048576LL, 2, 0, 4, 16, 2);
    reduce_mt<<<1024, 256>>>(mtp, mt2, MTPL);

    // 3) c_qr (4096x1024) = c_q @ W_qr^T   [bf16 planes]
    gemm_t6<256, false, true, false><<<128, blk, GSMEM>>>(
        cqkv2, CQKVPL, wqr2, WQRPL, nullptr, cqr2, CQRPL,
        512, 1280, 512, 1024, 0, 0, 0, 0, 0, 0, 1, 0, 4, 32, 1);

    // 4+5) qh AND kh in ONE persistent launch (z<4: qh; z>=4: kh)
    gemm_t6<256, false, true, true><<<148, blk, GSMEM>>>(
        cqkv2, CQKVPL, wuqT2, WUQPL, nullptr, qh2, HPL,
        512, 1280, 512, 192,
        576, 1024LL * 1280,
        (long long)(wuk2 - wuqT2), 0,
        (long long)(kh2 - qh2), 16LL * HZ, 4, HZ, 8, 8, 8);

    // 6) rope tails
    rope_q_kernel<<<8192, 256>>>(cqr2, CQRPL, fc, fs, qh2, HPL);
    rope_k_kernel<<<512, 256>>>(cqkv2, CQKVPL, fc, fs, kh2, HPL);

    // 7) VT[b,h] (128x1024) = MT[h-slice] @ c_kv[b]^T
    gemm_t6<256, false, true, false><<<148, blk, GSMEM>>>(
        mt2, MTPL, cqkv2 + 576, CQKVPL, nullptr, vt2, VTPL,
        512, 512, 1280, 1024,
        0, 128LL * 512, 1024LL * 1280, 0, 16LL * VTZ, VTZ, 16, 0, 4, 1, 64);

    // 8) fused flash attention
    flash_attn<<<148, blk, FSMEM>>>(qh2, kh2, vt2, out);
}